// round 12
// baseline (speedup 1.0000x reference)
#include <cuda_runtime.h>
#include <stdint.h>

#define BATCH   32768
#define NTREE   256
#define NNODE   2047
#define NFEAT   256
#define NCLS    8
#define DEPTH   10
#define SCHUNK  128
#define THREADS 512           // 128 samples x 4 lane-groups (3/3/2/2 trees each)
#define GT      10            // trees per staged group (last group ragged: 6)
#define NG      26            // ceil(256/10)
#define NCHUNK  (BATCH / SCHUNK)          // 256
#define NITEMS  (NCHUNK * NG)             // 6656, chunk-major
#define NSLOT   1024          // 8KB slab per tree (1023 internal nodes used)

// smem map: [0,128K) x-tile | [128K,+80K) node buffer | idx x2 | mbar
#define SM_X      0
#define SM_NODES  131072
#define SM_IDX    (131072 + 81920)           // 212992
#define IDX_PITCH 11
#define IDX_BYTES (SCHUNK * IDX_PITCH * 4)   // 5632
#define SM_MBAR   (SM_IDX + 2 * IDX_BYTES)   // 224256
#define SM_TOTAL  (SM_MBAR + 16)             // 224272

__device__ uint2 g_nodes2[NTREE * NSLOT];   // internal nodes: {thr bits, feat*512}
__device__ float g_xT[NFEAT * BATCH];       // x transposed [feature][sample]

// ---------------- merged prep: transpose x + pack nodes ----------------
__global__ void prep_k(const float* __restrict__ x,
                       const int* __restrict__ features,
                       const float* __restrict__ thresholds) {
    int b = blockIdx.x;
    const int TBLK = (NFEAT / 32) * (BATCH / 32);
    if (b < TBLK) {
        __shared__ float tile[32][33];
        int f0 = (b & 7) * 32, s0 = (b >> 3) * 32;
        int lx = threadIdx.x & 31, ly = threadIdx.x >> 5;   // 256 threads
        #pragma unroll
        for (int k = ly; k < 32; k += 8)
            tile[k][lx] = x[(size_t)(s0 + k) * NFEAT + f0 + lx];
        __syncthreads();
        #pragma unroll
        for (int k = ly; k < 32; k += 8)
            g_xT[(size_t)(f0 + k) * BATCH + s0 + lx] = tile[lx][k];
    } else {
        int i = (b - TBLK) * 256 + threadIdx.x;
        if (i < NTREE * 1023) {
            int t = i / 1023;
            int n = i - t * 1023;
            int src = t * NNODE + n;
            uint2 v;
            v.x = __float_as_uint(thresholds[src]);
            v.y = (unsigned)features[src] * (SCHUNK * 4);
            g_nodes2[t * NSLOT + n] = v;
        }
    }
}

// ---------------- helpers ----------------
__device__ __forceinline__ void stage_x(char* sm, int s0, int tid) {
    float4* xs4 = (float4*)(sm + SM_X);
    #pragma unroll
    for (int j = 0; j < 16; j++) {
        int i4 = tid + THREADS * j;                 // 8192 float4
        int f = i4 >> 5, o = i4 & 31;
        xs4[i4] = *(const float4*)(g_xT + (size_t)f * BATCH + s0 + o * 4);
    }
}

__device__ __forceinline__ void bulk_fetch_nodes(unsigned dst, int t0, unsigned bytes,
                                                 unsigned mbar) {
    asm volatile("mbarrier.arrive.expect_tx.shared.b64 _, [%0], %1;"
                 :: "r"(mbar), "r"(bytes) : "memory");
    const char* src = (const char*)(g_nodes2 + (size_t)t0 * NSLOT);
    asm volatile("cp.async.bulk.shared::cta.global.mbarrier::complete_tx::bytes "
                 "[%0], [%1], %2, [%3];"
                 :: "r"(dst), "l"(src), "r"(bytes), "r"(mbar) : "memory");
}

__device__ __forceinline__ void mbar_wait(unsigned mbar, unsigned parity) {
    unsigned done;
    asm volatile("{\n\t.reg .pred p;\n\t"
                 "mbarrier.try_wait.parity.acquire.cta.shared::cta.b64 p, [%1], %2;\n\t"
                 "selp.b32 %0, 1, 0, p;\n\t}"
                 : "=r"(done) : "r"(mbar), "r"(parity) : "memory");
    if (!done) {
        asm volatile("{\n\t.reg .pred P1;\n\t"
                     "W%=:\n\t"
                     "mbarrier.try_wait.parity.acquire.cta.shared::cta.b64 P1, [%0], %1, 0x989680;\n\t"
                     "@P1 bra.uni D%=;\n\t"
                     "bra.uni W%=;\n\t"
                     "D%=:\n\t}"
                     :: "r"(mbar), "r"(parity) : "memory");
    }
}

// one traversal step for a chain
#define STEP(o, c) do {                                                     \
    unsigned nx_, ny_;                                                      \
    asm("ld.shared.v2.u32 {%0,%1}, [%2];" : "=r"(nx_), "=r"(ny_) : "r"(o)); \
    float fv_;                                                              \
    asm("ld.shared.f32 %0, [%1];" : "=f"(fv_) : "r"(xaddr + ny_));          \
    o = o * 2u + c + ((fv_ >= __uint_as_float(nx_)) ? 8u : 0u);             \
} while (0)

// ---------------- main traversal (persistent) ----------------
__global__ __launch_bounds__(THREADS, 1)
void traverse_k(const float* __restrict__ values, float* __restrict__ out, int nsm) {
    extern __shared__ char sm[];
    int tid = threadIdx.x;

    unsigned smbase;
    asm("{ .reg .u64 t; cvta.to.shared.u64 t, %1; cvt.u32.u64 %0, t; }"
        : "=r"(smbase) : "l"(sm));
    unsigned mbar = smbase + SM_MBAR;

    int istart = (int)((long long)blockIdx.x * NITEMS / nsm);
    int iend   = (int)((long long)(blockIdx.x + 1) * NITEMS / nsm);

    int sl = tid & (SCHUNK - 1);
    int q  = tid >> 7;                          // lane-group 0..3
    unsigned xaddr = smbase + SM_X + sl * 4;
    int nch   = (q < 2) ? 3 : 2;                // chains this thread owns
    int tbase = (q < 2) ? 3 * q : 2 * q + 2;    // first tree-in-group: 0,3,6,8
    unsigned b0 = smbase + SM_NODES + (tbase + 0) * (NSLOT * 8);
    unsigned b1 = smbase + SM_NODES + (tbase + 1) * (NSLOT * 8);
    unsigned b2 = smbase + SM_NODES + (tbase + 2) * (NSLOT * 8);  // used iff nch==3
    unsigned c0 = 8u - b0, c1 = 8u - b1, c2 = 8u - b2;

    // prologue
    if (tid == 0)
        asm volatile("mbarrier.init.shared.b64 [%0], 1;" :: "r"(mbar) : "memory");
    __syncthreads();
    {
        int g0 = istart - (istart / NG) * NG;
        int nt0 = (g0 == NG - 1) ? (NTREE - (NG - 1) * GT) : GT;
        if (tid == 0)
            bulk_fetch_nodes(smbase + SM_NODES, g0 * GT, (unsigned)nt0 * (NSLOT * 8), mbar);
    }
    int cur_chunk = istart / NG;
    stage_x(sm, cur_chunk * SCHUNK, tid);
    __syncthreads();                            // x visible

    float4 vreg[5];
    float* prev_obase = out;
    int prev_nt = 0;

    for (int i = istart; i < iend; i++) {
        int k = i - istart;
        int chunk = i / NG;
        int g = i - chunk * NG;
        int s0 = chunk * SCHUNK;
        int t0 = g * GT;
        int nt = (g == NG - 1) ? (NTREE - (NG - 1) * GT) : GT;   // 10 or 6

        if (chunk != cur_chunk) {               // all threads past prev barrier
            stage_x(sm, s0, tid);
            cur_chunk = chunk;
            __syncthreads();
        }

        // issue prev item's values gather (long-latency LDGs before the wait)
        if (i > istart) {
            const unsigned* rb = (const unsigned*)(sm + SM_IDX + ((i - 1) & 1) * IDX_BYTES);
            #pragma unroll
            for (int j = 0; j < 5; j++) {
                int e = tid + THREADS * j;      // 0..2559
                int sl2 = e / (2 * GT);
                int r = e - sl2 * (2 * GT);
                int tg = r >> 1;
                if (tg < prev_nt) {
                    unsigned vrow = rb[sl2 * IDX_PITCH + tg];
                    vreg[j] = __ldg((const float4*)values + (size_t)vrow * 2 + (r & 1));
                }
            }
        }

        mbar_wait(mbar, (unsigned)(k & 1));     // nodes[i] staged (acquire)

        // ---- traversal: 2 or 3 interleaved chains (warp-uniform branch)
        unsigned leaf0, leaf1, leaf2 = 0;
        if (q < 2) {
            unsigned o0 = b0, o1 = b1, o2 = b2;
            #pragma unroll
            for (int d = 0; d < DEPTH; d++) { STEP(o0, c0); STEP(o1, c1); STEP(o2, c2); }
            leaf0 = (o0 - b0) >> 3; leaf1 = (o1 - b1) >> 3; leaf2 = (o2 - b2) >> 3;
        } else {
            unsigned o0 = b0, o1 = b1;
            #pragma unroll
            for (int d = 0; d < DEPTH; d++) { STEP(o0, c0); STEP(o1, c1); }
            leaf0 = (o0 - b0) >> 3; leaf1 = (o1 - b1) >> 3;
        }

        // ---- store prev item's gathered values (coalesced-ish)
        if (i > istart) {
            #pragma unroll
            for (int j = 0; j < 5; j++) {
                int e = tid + THREADS * j;
                int sl2 = e / (2 * GT);
                int r = e - sl2 * (2 * GT);
                int tg = r >> 1;
                if (tg < prev_nt)
                    *(float4*)(prev_obase + (size_t)sl2 * (NTREE * NCLS) + tg * NCLS
                               + (r & 1) * 4) = vreg[j];
            }
        }

        // ---- publish this item's values-row indices (pitch 11, conflict-free)
        {
            unsigned* wb = (unsigned*)(sm + SM_IDX + (i & 1) * IDX_BYTES);
            wb[sl * IDX_PITCH + tbase + 0] = (unsigned)(t0 + tbase + 0) * NNODE + leaf0;
            wb[sl * IDX_PITCH + tbase + 1] = (unsigned)(t0 + tbase + 1) * NNODE + leaf1;
            if (q < 2)
                wb[sl * IDX_PITCH + tbase + 2] = (unsigned)(t0 + tbase + 2) * NNODE + leaf2;
        }
        __syncthreads();                        // idx visible; node reads done

        if (i + 1 < iend && tid == 0) {
            int gn = (i + 1) - ((i + 1) / NG) * NG;
            int ntn = (gn == NG - 1) ? (NTREE - (NG - 1) * GT) : GT;
            bulk_fetch_nodes(smbase + SM_NODES, gn * GT, (unsigned)ntn * (NSLOT * 8), mbar);
        }

        prev_obase = out + (size_t)s0 * (NTREE * NCLS) + t0 * NCLS;
        prev_nt = nt;
    }

    // epilogue: gather + store for the last item
    {
        const unsigned* rb = (const unsigned*)(sm + SM_IDX + ((iend - 1) & 1) * IDX_BYTES);
        #pragma unroll
        for (int j = 0; j < 5; j++) {
            int e = tid + THREADS * j;
            int sl2 = e / (2 * GT);
            int r = e - sl2 * (2 * GT);
            int tg = r >> 1;
            if (tg < prev_nt) {
                unsigned vrow = rb[sl2 * IDX_PITCH + tg];
                vreg[j] = __ldg((const float4*)values + (size_t)vrow * 2 + (r & 1));
                *(float4*)(prev_obase + (size_t)sl2 * (NTREE * NCLS) + tg * NCLS
                           + (r & 1) * 4) = vreg[j];
            }
        }
    }
}

extern "C" void kernel_launch(void* const* d_in, const int* in_sizes, int n_in,
                              void* d_out, int out_size) {
    // metadata order: x, lefts, rights, features, thresholds, values, nodes_offset
    const float* x          = (const float*)d_in[0];
    const int*   features   = (const int*)  d_in[3];
    const float* thresholds = (const float*)d_in[4];
    const float* values     = (const float*)d_in[5];

    static int nsm = 0;                        // deterministic per-device constant
    if (nsm == 0) {
        int dev = 0;
        cudaGetDevice(&dev);
        cudaDeviceGetAttribute(&nsm, cudaDevAttrMultiProcessorCount, dev);
        if (nsm <= 0) nsm = 148;
    }

    cudaFuncSetAttribute(traverse_k, cudaFuncAttributeMaxDynamicSharedMemorySize, SM_TOTAL);

    int prep_blocks = (NFEAT / 32) * (BATCH / 32) + (NTREE * 1023 + 255) / 256;
    prep_k<<<prep_blocks, 256>>>(x, features, thresholds);
    traverse_k<<<nsm, THREADS, SM_TOTAL>>>(values, (float*)d_out, nsm);
}